// round 15
// baseline (speedup 1.0000x reference)
#include <cuda_runtime.h>
#include <cuda_fp16.h>
#include <cstdint>

#define BB   32
#define TQQ  2000
#define TKK  512
#define EXNEG (-2000000)
#define PBLANK 0.36787944117144233f   /* e^-1 */
#define EF 2.7182818284590452f        /* e */
#define FULLW 0xffffffffu
#define RSTRIDE 20                    /* record slot stride in floats (80B) */

__device__ float    g_loss[BB];
__device__ float    g_logz[BB * TQQ];
__device__ uint2    g_emit[(size_t)BB * TQQ * 128];  // fp16x4 e^{x+1}, masked
__device__ unsigned g_ctr = 0;

__device__ __forceinline__ float2 h2f_(unsigned u) {
    __half2 h = *reinterpret_cast<__half2*>(&u);
    return __half22float2(h);
}

// ---------------------------------------------------------------------------
// Kernel 1: per-row logZ = log(e^-1 + sum_{j<kl} exp(x))  AND  emission
// store g_emit[b,t,j] = half(e^{x+1}) masked to 0 for j >= kl.
// ---------------------------------------------------------------------------
__global__ __launch_bounds__(256) void zlog_kernel(const float* __restrict__ attn,
                                                   const int* __restrict__ in_lens,
                                                   const int* __restrict__ out_lens) {
    int b    = blockIdx.y;
    int warp = threadIdx.x >> 5;
    int lane = threadIdx.x & 31;
    int t    = blockIdx.x * 8 + warp;
    if (t >= TQQ) return;
    int kl = min(max(in_lens[b], 1), TKK);
    int ql = min(max(out_lens[b], 1), TQQ);
    if (t >= ql) return;

    const float4* row  = (const float4*)(attn + ((size_t)b * TQQ + t) * TKK);
    uint2*        erow = g_emit + ((size_t)b * TQQ + t) * 128;
    float s = 0.f;
#pragma unroll
    for (int k = 0; k < 4; k++) {
        if (128 * k < kl) {
            float4 v = __ldg(row + lane + 32 * k);
            int j = 4 * (lane + 32 * k);
            float a0 = (j + 0 < kl) ? __expf(v.x) : 0.f;
            float a1 = (j + 1 < kl) ? __expf(v.y) : 0.f;
            float a2 = (j + 2 < kl) ? __expf(v.z) : 0.f;
            float a3 = (j + 3 < kl) ? __expf(v.w) : 0.f;
            s += (a0 + a1) + (a2 + a3);
            __half2 p01 = __floats2half2_rn(a0 * EF, a1 * EF);
            __half2 p23 = __floats2half2_rn(a2 * EF, a3 * EF);
            uint2 w;
            w.x = *reinterpret_cast<unsigned*>(&p01);
            w.y = *reinterpret_cast<unsigned*>(&p23);
            erow[lane + 32 * k] = w;
        } else {
            erow[lane + 32 * k] = make_uint2(0u, 0u);
        }
    }
#pragma unroll
    for (int o = 16; o; o >>= 1) s += __shfl_xor_sync(FULLW, s, o);
    if (lane == 0) g_logz[b * TQQ + t] = __logf(PBLANK + s);
}

// ---------------------------------------------------------------------------
// Kernel 2: CTC forward recursion. B-domain, 4 steps per exchange/barrier,
// lazy block floating point, precomputed fp16 emissions (no MUFU in loop),
// 8-row uint2 prefetch with pointer refill, smem-record halo exchange.
// Invariant: true_state = c8[j] * 2^(exo - kk).
// ---------------------------------------------------------------------------
__global__ __launch_bounds__(128, 1) void dp_kernel(const float* __restrict__ attn,
                                                    const int* __restrict__ in_lens,
                                                    const int* __restrict__ out_lens,
                                                    float* __restrict__ out) {
    __shared__ float rec[2][129 * RSTRIDE];
    __shared__ float sm_even[513];
    __shared__ float sm_odd[513];
    __shared__ int   sm_ex[513];
    __shared__ float red[128];

    int b    = blockIdx.x;
    int tid  = threadIdx.x;
    int warp = tid >> 5;
    int kl = min(max(in_lens[b], 1), TKK);
    int ql = min(max(out_lens[b], 1), TQQ);

    const uint2* eb = g_emit + (size_t)b * TQQ * 128 + tid;

    bool wact = (128 * warp) <= kl;

    if (tid < 2) {
        float4* z = (float4*)&rec[tid][0];
        z[0] = make_float4(0.f, 0.f, 0.f, 0.f);
        z[1] = make_float4(0.f, 0.f, 0.f, 0.f);
        z[2] = make_float4(__int_as_float(EXNEG), 0.f, 0.f, 0.f);
        z[3] = make_float4(0.f, 0.f, 0.f, 0.f);     // kk = 0
    }

    // ---- row 0 init (B_0 = A_0) ----
    float c8[8];
#pragma unroll
    for (int k = 0; k < 8; k++) c8[k] = 0.f;
    float a1024 = 0.f;
    int   exo   = EXNEG;
    int   kk    = 0;
    if (tid == 0) {
        c8[0] = PBLANK;
        c8[1] = __expf(__ldg(attn + (size_t)b * TQQ * TKK));
        exo = 0;
    }

    // ---- prefetch rows 1..8 (fp16 emissions, 8B per row) ----
    int qm = ql - 1;
    uint2 xs0 = __ldg(eb + (size_t)min(1, qm) * 128);
    uint2 xs1 = __ldg(eb + (size_t)min(2, qm) * 128);
    uint2 xs2 = __ldg(eb + (size_t)min(3, qm) * 128);
    uint2 xs3 = __ldg(eb + (size_t)min(4, qm) * 128);
    uint2 xs4 = __ldg(eb + (size_t)min(5, qm) * 128);
    uint2 xs5 = __ldg(eb + (size_t)min(6, qm) * 128);
    uint2 xs6 = __ldg(eb + (size_t)min(7, qm) * 128);
    uint2 xs7 = __ldg(eb + (size_t)min(8, qm) * 128);

    const uint2* rp = eb + (size_t)9 * 128;
    int t = 1;

#define PAIRS(DST, SRC, J, EM)                                                 \
    { float se_ = SRC[J] + SRC[J - 1]; DST[J] = se_;                           \
      DST[J + 1] = (SRC[J + 1] + se_) * (EM); }

#define GROUP(S0, S1, S2, S3, REFILL, GUARDED)                                 \
    {                                                                          \
        int p_ = ((t - 1) >> 2) & 1;                                           \
        float e00, e01, e02, e03, e10, e11, e12, e13;                          \
        float e20, e21, e22, e23, e30, e31, e32, e33;                          \
        if (wact) {                                                            \
            float2 r_;                                                         \
            r_ = h2f_((S0).x); e00 = r_.x; e01 = r_.y;                         \
            r_ = h2f_((S0).y); e02 = r_.x; e03 = r_.y;                         \
            r_ = h2f_((S1).x); e10 = r_.x; e11 = r_.y;                         \
            r_ = h2f_((S1).y); e12 = r_.x; e13 = r_.y;                         \
            r_ = h2f_((S2).x); e20 = r_.x; e21 = r_.y;                         \
            r_ = h2f_((S2).y); e22 = r_.x; e23 = r_.y;                         \
            r_ = h2f_((S3).x); e30 = r_.x; e31 = r_.y;                         \
            r_ = h2f_((S3).y); e32 = r_.x; e33 = r_.y;                         \
            if ((REFILL) == 1) {                                               \
                (S0) = __ldg(rp);                                              \
                (S1) = __ldg(rp + 128);                                        \
                (S2) = __ldg(rp + 256);                                        \
                (S3) = __ldg(rp + 384);                                        \
                rp += 512;                                                     \
            } else if ((REFILL) == 2) {                                        \
                (S0) = __ldg(eb + (size_t)min(t + 8,  qm) * 128);              \
                (S1) = __ldg(eb + (size_t)min(t + 9,  qm) * 128);              \
                (S2) = __ldg(eb + (size_t)min(t + 10, qm) * 128);              \
                (S3) = __ldg(eb + (size_t)min(t + 11, qm) * 128);              \
            }                                                                  \
            float4* wb = (float4*)&rec[p_][(tid + 1) * RSTRIDE];               \
            wb[0] = make_float4(c8[0], c8[1], c8[2], c8[3]);                   \
            wb[1] = make_float4(c8[4], c8[5], c8[6], c8[7]);                   \
            wb[2] = make_float4(__int_as_float(exo), e01, e02, e03);           \
            wb[3] = make_float4(e12, e13, e23, __int_as_float(kk));            \
        }                                                                      \
        __syncthreads();                                                       \
        if (wact) {                                                            \
            const float4* rb = (const float4*)&rec[p_][tid * RSTRIDE];         \
            float4 q0 = rb[0], q1 = rb[1], q2 = rb[2], q3 = rb[3];             \
            float h_[8]; int he_, kkL_;                                        \
            h_[0] = q0.x; h_[1] = q0.y; h_[2] = q0.z; h_[3] = q0.w;            \
            h_[4] = q1.x; h_[5] = q1.y; h_[6] = q1.z; h_[7] = q1.w;            \
            he_  = __float_as_int(q2.x);                                       \
            kkL_ = __float_as_int(q3.w);                                       \
            float f01 = q2.y, f02 = q2.z, f03 = q2.w;                          \
            float f12 = q3.x, f13 = q3.y, f23 = q3.z;                          \
            int bse = max(exo, he_);                                           \
            int d0_ = 127 + (he_ - kkL_) - bse; if (d0_ < 0) d0_ = 0;          \
            int d1_ = 127 + (exo - kk)   - bse; if (d1_ < 0) d1_ = 0;          \
            float sh_ = __int_as_float(d0_ << 23);                             \
            float so_ = __int_as_float(d1_ << 23);                             \
            float A_[16], B_[16];                                              \
            A_[0] = h_[0] * sh_; A_[1] = h_[1] * sh_;                          \
            A_[2] = h_[2] * sh_; A_[3] = h_[3] * sh_;                          \
            A_[4] = h_[4] * sh_; A_[5] = h_[5] * sh_;                          \
            A_[6] = h_[6] * sh_; A_[7] = h_[7] * sh_;                          \
            A_[8]  = c8[0] * so_; A_[9]  = c8[1] * so_;                        \
            A_[10] = c8[2] * so_; A_[11] = c8[3] * so_;                        \
            A_[12] = c8[4] * so_; A_[13] = c8[5] * so_;                        \
            A_[14] = c8[6] * so_; A_[15] = c8[7] * so_;                        \
            float n4 = a1024 * so_;                                            \
            if (!(GUARDED) || (t + 0 < ql)) {                                  \
                PAIRS(B_, A_, 2, f01) PAIRS(B_, A_, 4, f02)                    \
                PAIRS(B_, A_, 6, f03)                                          \
                PAIRS(B_, A_, 8, e00) PAIRS(B_, A_, 10, e01)                   \
                PAIRS(B_, A_, 12, e02) PAIRS(B_, A_, 14, e03)                  \
                n4 = n4 + A_[15];                                              \
            } else {                                                           \
                _Pragma("unroll")                                              \
                for (int j_ = 2; j_ < 16; j_++) B_[j_] = A_[j_];               \
            }                                                                  \
            if (!(GUARDED) || (t + 1 < ql)) {                                  \
                PAIRS(A_, B_, 4, f12) PAIRS(A_, B_, 6, f13)                    \
                PAIRS(A_, B_, 8, e10) PAIRS(A_, B_, 10, e11)                   \
                PAIRS(A_, B_, 12, e12) PAIRS(A_, B_, 14, e13)                  \
                n4 = n4 + B_[15];                                              \
            } else {                                                           \
                _Pragma("unroll")                                              \
                for (int j_ = 4; j_ < 16; j_++) A_[j_] = B_[j_];               \
            }                                                                  \
            if (!(GUARDED) || (t + 2 < ql)) {                                  \
                PAIRS(B_, A_, 6, f23)                                          \
                PAIRS(B_, A_, 8, e20) PAIRS(B_, A_, 10, e21)                   \
                PAIRS(B_, A_, 12, e22) PAIRS(B_, A_, 14, e23)                  \
                n4 = n4 + A_[15];                                              \
            } else {                                                           \
                _Pragma("unroll")                                              \
                for (int j_ = 6; j_ < 16; j_++) B_[j_] = A_[j_];               \
            }                                                                  \
            if (!(GUARDED) || (t + 3 < ql)) {                                  \
                PAIRS(A_, B_, 8, e30) PAIRS(A_, B_, 10, e31)                   \
                PAIRS(A_, B_, 12, e32) PAIRS(A_, B_, 14, e33)                  \
                n4 = n4 + B_[15];                                              \
            } else {                                                           \
                _Pragma("unroll")                                              \
                for (int j_ = 8; j_ < 16; j_++) A_[j_] = B_[j_];               \
            }                                                                  \
            float m_ = fmaxf(fmaxf(fmaxf(A_[8], A_[9]), fmaxf(A_[10], A_[11])),\
                             fmaxf(fmaxf(A_[12], A_[13]),                      \
                                   fmaxf(A_[14], A_[15])));                    \
            m_ = fmaxf(m_, n4);                                                \
            c8[0] = A_[8];  c8[1] = A_[9];                                     \
            c8[2] = A_[10]; c8[3] = A_[11];                                    \
            c8[4] = A_[12]; c8[5] = A_[13];                                    \
            c8[6] = A_[14]; c8[7] = A_[15];                                    \
            a1024 = n4;                                                        \
            kk  = ((__float_as_int(m_) >> 23) & 255) - 127;                    \
            exo = bse + kk;                                                    \
        }                                                                      \
        t += 4;                                                                \
    }

    while (t + 15 < ql) {
        GROUP(xs0, xs1, xs2, xs3, 1, 0)
        GROUP(xs4, xs5, xs6, xs7, 1, 0)
    }
    while (t + 7 < ql) {
        GROUP(xs0, xs1, xs2, xs3, 2, 0)
        GROUP(xs4, xs5, xs6, xs7, 2, 0)
    }
    if (t + 3 < ql) {
        GROUP(xs0, xs1, xs2, xs3, 0, 0)
        if (t < ql) { GROUP(xs4, xs5, xs6, xs7, 0, 1) }
    } else if (t < ql) {
        GROUP(xs0, xs1, xs2, xs3, 0, 1)
    }

    // ---- epilogue: true exponent of stored mantissas is exo - kk ----
#pragma unroll
    for (int k = 0; k < 4; k++) {
        sm_even[tid * 4 + k] = c8[2 * k];
        sm_odd [tid * 4 + k] = c8[2 * k + 1];
        sm_ex  [tid * 4 + k] = exo - kk;
    }
    if (tid == 127) { sm_even[512] = a1024; sm_odd[512] = 0.f; sm_ex[512] = exo - kk; }

    float lz = 0.f;
    for (int tt = tid; tt < ql; tt += 128) lz += g_logz[b * TQQ + tt];
    red[tid] = lz;
    __syncthreads();
#pragma unroll
    for (int s = 64; s; s >>= 1) {
        if (tid < s) red[tid] += red[tid + s];
        __syncthreads();
    }

    if (tid == 0) {
        float mE = sm_even[kl];     int eE = sm_ex[kl];       // state 2kl
        float mL = sm_odd[kl - 1];  int eL = sm_ex[kl - 1];   // state 2kl-1
        double ll;
        if (mE == 0.f && mL == 0.f) {
            ll = -1e9;
        } else {
            int eM = max(mE > 0.f ? eE : EXNEG, mL > 0.f ? eL : EXNEG);
            double s2 = 0.0;
            if (mE > 0.f) s2 += (double)mE * exp2((double)(eE - eM));
            if (mL > 0.f) s2 += (double)mL * exp2((double)(eL - eM));
            ll = log(s2) + (double)eM * 0.6931471805599453;
        }
        ll -= (double)red[0];          // - sum_t log Z_t
        ll -= (double)(ql - 1);        // undo B = A * e^t rescale
        g_loss[b] = (float)(-ll / (double)kl);

        __threadfence();
        unsigned prev = atomicAdd(&g_ctr, 1u);
        if (prev == BB - 1) {
            g_ctr = 0;
            __threadfence();
            float s = 0.f;
            for (int bb = 0; bb < BB; bb++) s += g_loss[bb];
            out[0] = s / (float)BB;
        }
    }
}

extern "C" void kernel_launch(void* const* d_in, const int* in_sizes, int n_in,
                              void* d_out, int out_size) {
    const float* attn     = (const float*)d_in[0];
    const int*   in_lens  = (const int*)d_in[1];
    const int*   out_lens = (const int*)d_in[2];

    zlog_kernel<<<dim3((TQQ + 7) / 8, BB), 256>>>(attn, in_lens, out_lens);
    dp_kernel<<<BB, 128>>>(attn, in_lens, out_lens, (float*)d_out);
}

// round 16
// speedup vs baseline: 1.2677x; 1.2677x over previous
#include <cuda_runtime.h>
#include <cstdint>

#define BB   32
#define TQQ  2000
#define TKK  512
#define EXNEG (-2000000)
#define PBLANK 0.36787944117144233f   /* e^-1 */
#define EF 2.7182818284590452f        /* e */
#define FULLW 0xffffffffu
#define RSTRIDE 20                    /* record slot stride in floats (80B) */

__device__ float    g_loss[BB];
__device__ float    g_logz[BB * TQQ];
__device__ float    g_emit[(size_t)BB * TQQ * TKK];  // fp32 e^{x+1}, masked
__device__ unsigned g_ctr = 0;

// ---------------------------------------------------------------------------
// Kernel 1: per-row logZ = log(e^-1 + sum_{j<kl} exp(x))  AND  fp32 emission
// store g_emit[b,t,j] = (j<kl) ? e^{x+1} : 0   for rows t < ql.
// ---------------------------------------------------------------------------
__global__ __launch_bounds__(256) void zlog_kernel(const float* __restrict__ attn,
                                                   const int* __restrict__ in_lens,
                                                   const int* __restrict__ out_lens) {
    int b    = blockIdx.y;
    int warp = threadIdx.x >> 5;
    int lane = threadIdx.x & 31;
    int t    = blockIdx.x * 8 + warp;
    if (t >= TQQ) return;
    int kl = min(max(in_lens[b], 1), TKK);
    int ql = min(max(out_lens[b], 1), TQQ);
    if (t >= ql) return;

    const float4* row  = (const float4*)(attn + ((size_t)b * TQQ + t) * TKK);
    float4*       erow = (float4*)(g_emit + ((size_t)b * TQQ + t) * TKK);
    float s = 0.f;
#pragma unroll
    for (int k = 0; k < 4; k++) {
        if (128 * k < kl) {
            float4 v = __ldg(row + lane + 32 * k);
            int j = 4 * (lane + 32 * k);
            float a0 = (j + 0 < kl) ? __expf(v.x) : 0.f;
            float a1 = (j + 1 < kl) ? __expf(v.y) : 0.f;
            float a2 = (j + 2 < kl) ? __expf(v.z) : 0.f;
            float a3 = (j + 3 < kl) ? __expf(v.w) : 0.f;
            s += (a0 + a1) + (a2 + a3);
            erow[lane + 32 * k] = make_float4(a0 * EF, a1 * EF, a2 * EF, a3 * EF);
        } else {
            erow[lane + 32 * k] = make_float4(0.f, 0.f, 0.f, 0.f);
        }
    }
#pragma unroll
    for (int o = 16; o; o >>= 1) s += __shfl_xor_sync(FULLW, s, o);
    if (lane == 0) g_logz[b * TQQ + t] = __logf(PBLANK + s);
}

// ---------------------------------------------------------------------------
// Kernel 2: CTC forward recursion. B-domain, 4 steps per exchange/barrier,
// lazy block floating point, PRECOMPUTED fp32 emissions (zero XU/MUFU work
// in the serial loop), 8-row prefetch with pointer refill, smem-record halo
// exchange. Invariant: true_state = c8[j] * 2^(exo - kk).
// ---------------------------------------------------------------------------
__global__ __launch_bounds__(128, 1) void dp_kernel(const float* __restrict__ attn,
                                                    const int* __restrict__ in_lens,
                                                    const int* __restrict__ out_lens,
                                                    float* __restrict__ out) {
    __shared__ float rec[2][129 * RSTRIDE];
    __shared__ float sm_even[513];
    __shared__ float sm_odd[513];
    __shared__ int   sm_ex[513];
    __shared__ float red[128];

    int b    = blockIdx.x;
    int tid  = threadIdx.x;
    int warp = tid >> 5;
    int kl = min(max(in_lens[b], 1), TKK);
    int ql = min(max(out_lens[b], 1), TQQ);

    const float4* eb = (const float4*)(g_emit + (size_t)b * TQQ * TKK) + tid;

    bool wact = (128 * warp) <= kl;

    if (tid < 2) {
        float4* z = (float4*)&rec[tid][0];
        z[0] = make_float4(__int_as_float(EXNEG), 0.f, 0.f, 0.f);  // exo, kk, f01, f02
        z[1] = make_float4(0.f, 0.f, 0.f, 0.f);
        z[2] = make_float4(0.f, 0.f, 0.f, 0.f);
        z[3] = make_float4(0.f, 0.f, 0.f, 0.f);
    }

    // ---- row 0 init (B_0 = A_0) ----
    float c8[8];
#pragma unroll
    for (int k = 0; k < 8; k++) c8[k] = 0.f;
    float a1024 = 0.f;
    int   exo   = EXNEG;
    int   kk    = 0;
    if (tid == 0) {
        c8[0] = PBLANK;
        c8[1] = __expf(__ldg(attn + (size_t)b * TQQ * TKK));
        exo = 0;
    }

    // ---- prefetch rows 1..8 (fp32 emissions, 16B per row per thread) ----
    int qm = ql - 1;
    float4 xs0 = __ldg(eb + (size_t)min(1, qm) * 128);
    float4 xs1 = __ldg(eb + (size_t)min(2, qm) * 128);
    float4 xs2 = __ldg(eb + (size_t)min(3, qm) * 128);
    float4 xs3 = __ldg(eb + (size_t)min(4, qm) * 128);
    float4 xs4 = __ldg(eb + (size_t)min(5, qm) * 128);
    float4 xs5 = __ldg(eb + (size_t)min(6, qm) * 128);
    float4 xs6 = __ldg(eb + (size_t)min(7, qm) * 128);
    float4 xs7 = __ldg(eb + (size_t)min(8, qm) * 128);

    const float4* rp = eb + (size_t)9 * 128;
    int t = 1;

#define PAIRS(DST, SRC, J, EM)                                                 \
    { float se_ = SRC[J] + SRC[J - 1]; DST[J] = se_;                           \
      DST[J + 1] = (SRC[J + 1] + se_) * (EM); }

#define GROUP(S0, S1, S2, S3, REFILL, GUARDED)                                 \
    {                                                                          \
        int p_ = ((t - 1) >> 2) & 1;                                           \
        float e00, e01, e02, e03, e10, e11, e12, e13;                          \
        float e20, e21, e22, e23, e30, e31, e32, e33;                          \
        if (wact) {                                                            \
            e00 = (S0).x; e01 = (S0).y; e02 = (S0).z; e03 = (S0).w;            \
            e10 = (S1).x; e11 = (S1).y; e12 = (S1).z; e13 = (S1).w;            \
            e20 = (S2).x; e21 = (S2).y; e22 = (S2).z; e23 = (S2).w;            \
            e30 = (S3).x; e31 = (S3).y; e32 = (S3).z; e33 = (S3).w;            \
            if ((REFILL) == 1) {                                               \
                (S0) = __ldg(rp);                                              \
                (S1) = __ldg(rp + 128);                                        \
                (S2) = __ldg(rp + 256);                                        \
                (S3) = __ldg(rp + 384);                                        \
                rp += 512;                                                     \
            } else if ((REFILL) == 2) {                                        \
                (S0) = __ldg(eb + (size_t)min(t + 8,  qm) * 128);              \
                (S1) = __ldg(eb + (size_t)min(t + 9,  qm) * 128);              \
                (S2) = __ldg(eb + (size_t)min(t + 10, qm) * 128);              \
                (S3) = __ldg(eb + (size_t)min(t + 11, qm) * 128);              \
            }                                                                  \
            float4* wb = (float4*)&rec[p_][(tid + 1) * RSTRIDE];               \
            wb[0] = make_float4(__int_as_float(exo), __int_as_float(kk),       \
                                e01, e02);                                     \
            wb[1] = make_float4(c8[0], c8[1], c8[2], c8[3]);                   \
            wb[2] = make_float4(c8[4], c8[5], c8[6], c8[7]);                   \
            wb[3] = make_float4(e03, e12, e13, e23);                           \
        }                                                                      \
        __syncthreads();                                                       \
        if (wact) {                                                            \
            const float4* rb = (const float4*)&rec[p_][tid * RSTRIDE];         \
            float4 q0 = rb[0], q1 = rb[1], q2 = rb[2], q3 = rb[3];             \
            int he_  = __float_as_int(q0.x);                                   \
            int kkL_ = __float_as_int(q0.y);                                   \
            float f01 = q0.z, f02 = q0.w;                                      \
            float h_[8];                                                       \
            h_[0] = q1.x; h_[1] = q1.y; h_[2] = q1.z; h_[3] = q1.w;            \
            h_[4] = q2.x; h_[5] = q2.y; h_[6] = q2.z; h_[7] = q2.w;            \
            float f03 = q3.x, f12 = q3.y, f13 = q3.z, f23 = q3.w;              \
            int bse = max(exo, he_);                                           \
            int d0_ = 127 + (he_ - kkL_) - bse; if (d0_ < 0) d0_ = 0;          \
            int d1_ = 127 + (exo - kk)   - bse; if (d1_ < 0) d1_ = 0;          \
            float sh_ = __int_as_float(d0_ << 23);                             \
            float so_ = __int_as_float(d1_ << 23);                             \
            float A_[16], B_[16];                                              \
            A_[0] = h_[0] * sh_; A_[1] = h_[1] * sh_;                          \
            A_[2] = h_[2] * sh_; A_[3] = h_[3] * sh_;                          \
            A_[4] = h_[4] * sh_; A_[5] = h_[5] * sh_;                          \
            A_[6] = h_[6] * sh_; A_[7] = h_[7] * sh_;                          \
            A_[8]  = c8[0] * so_; A_[9]  = c8[1] * so_;                        \
            A_[10] = c8[2] * so_; A_[11] = c8[3] * so_;                        \
            A_[12] = c8[4] * so_; A_[13] = c8[5] * so_;                        \
            A_[14] = c8[6] * so_; A_[15] = c8[7] * so_;                        \
            float n4 = a1024 * so_;                                            \
            if (!(GUARDED) || (t + 0 < ql)) {                                  \
                PAIRS(B_, A_, 2, f01) PAIRS(B_, A_, 4, f02)                    \
                PAIRS(B_, A_, 6, f03)                                          \
                PAIRS(B_, A_, 8, e00) PAIRS(B_, A_, 10, e01)                   \
                PAIRS(B_, A_, 12, e02) PAIRS(B_, A_, 14, e03)                  \
                n4 = n4 + A_[15];                                              \
            } else {                                                           \
                _Pragma("unroll")                                              \
                for (int j_ = 2; j_ < 16; j_++) B_[j_] = A_[j_];               \
            }                                                                  \
            if (!(GUARDED) || (t + 1 < ql)) {                                  \
                PAIRS(A_, B_, 4, f12) PAIRS(A_, B_, 6, f13)                    \
                PAIRS(A_, B_, 8, e10) PAIRS(A_, B_, 10, e11)                   \
                PAIRS(A_, B_, 12, e12) PAIRS(A_, B_, 14, e13)                  \
                n4 = n4 + B_[15];                                              \
            } else {                                                           \
                _Pragma("unroll")                                              \
                for (int j_ = 4; j_ < 16; j_++) A_[j_] = B_[j_];               \
            }                                                                  \
            if (!(GUARDED) || (t + 2 < ql)) {                                  \
                PAIRS(B_, A_, 6, f23)                                          \
                PAIRS(B_, A_, 8, e20) PAIRS(B_, A_, 10, e21)                   \
                PAIRS(B_, A_, 12, e22) PAIRS(B_, A_, 14, e23)                  \
                n4 = n4 + A_[15];                                              \
            } else {                                                           \
                _Pragma("unroll")                                              \
                for (int j_ = 6; j_ < 16; j_++) B_[j_] = A_[j_];               \
            }                                                                  \
            if (!(GUARDED) || (t + 3 < ql)) {                                  \
                PAIRS(A_, B_, 8, e30) PAIRS(A_, B_, 10, e31)                   \
                PAIRS(A_, B_, 12, e32) PAIRS(A_, B_, 14, e33)                  \
                n4 = n4 + B_[15];                                              \
            } else {                                                           \
                _Pragma("unroll")                                              \
                for (int j_ = 8; j_ < 16; j_++) A_[j_] = B_[j_];               \
            }                                                                  \
            float m_ = fmaxf(fmaxf(fmaxf(A_[8], A_[9]), fmaxf(A_[10], A_[11])),\
                             fmaxf(fmaxf(A_[12], A_[13]),                      \
                                   fmaxf(A_[14], A_[15])));                    \
            m_ = fmaxf(m_, n4);                                                \
            c8[0] = A_[8];  c8[1] = A_[9];                                     \
            c8[2] = A_[10]; c8[3] = A_[11];                                    \
            c8[4] = A_[12]; c8[5] = A_[13];                                    \
            c8[6] = A_[14]; c8[7] = A_[15];                                    \
            a1024 = n4;                                                        \
            kk  = ((__float_as_int(m_) >> 23) & 255) - 127;                    \
            exo = bse + kk;                                                    \
        }                                                                      \
        t += 4;                                                                \
    }

    while (t + 15 < ql) {
        GROUP(xs0, xs1, xs2, xs3, 1, 0)
        GROUP(xs4, xs5, xs6, xs7, 1, 0)
    }
    while (t + 7 < ql) {
        GROUP(xs0, xs1, xs2, xs3, 2, 0)
        GROUP(xs4, xs5, xs6, xs7, 2, 0)
    }
    if (t + 3 < ql) {
        GROUP(xs0, xs1, xs2, xs3, 0, 0)
        if (t < ql) { GROUP(xs4, xs5, xs6, xs7, 0, 1) }
    } else if (t < ql) {
        GROUP(xs0, xs1, xs2, xs3, 0, 1)
    }

    // ---- epilogue: true exponent of stored mantissas is exo - kk ----
#pragma unroll
    for (int k = 0; k < 4; k++) {
        sm_even[tid * 4 + k] = c8[2 * k];
        sm_odd [tid * 4 + k] = c8[2 * k + 1];
        sm_ex  [tid * 4 + k] = exo - kk;
    }
    if (tid == 127) { sm_even[512] = a1024; sm_odd[512] = 0.f; sm_ex[512] = exo - kk; }

    float lz = 0.f;
    for (int tt = tid; tt < ql; tt += 128) lz += g_logz[b * TQQ + tt];
    red[tid] = lz;
    __syncthreads();
#pragma unroll
    for (int s = 64; s; s >>= 1) {
        if (tid < s) red[tid] += red[tid + s];
        __syncthreads();
    }

    if (tid == 0) {
        float mE = sm_even[kl];     int eE = sm_ex[kl];       // state 2kl
        float mL = sm_odd[kl - 1];  int eL = sm_ex[kl - 1];   // state 2kl-1
        double ll;
        if (mE == 0.f && mL == 0.f) {
            ll = -1e9;
        } else {
            int eM = max(mE > 0.f ? eE : EXNEG, mL > 0.f ? eL : EXNEG);
            double s2 = 0.0;
            if (mE > 0.f) s2 += (double)mE * exp2((double)(eE - eM));
            if (mL > 0.f) s2 += (double)mL * exp2((double)(eL - eM));
            ll = log(s2) + (double)eM * 0.6931471805599453;
        }
        ll -= (double)red[0];          // - sum_t log Z_t
        ll -= (double)(ql - 1);        // undo B = A * e^t rescale
        g_loss[b] = (float)(-ll / (double)kl);

        __threadfence();
        unsigned prev = atomicAdd(&g_ctr, 1u);
        if (prev == BB - 1) {
            g_ctr = 0;
            __threadfence();
            float s = 0.f;
            for (int bb = 0; bb < BB; bb++) s += g_loss[bb];
            out[0] = s / (float)BB;
        }
    }
}

extern "C" void kernel_launch(void* const* d_in, const int* in_sizes, int n_in,
                              void* d_out, int out_size) {
    const float* attn     = (const float*)d_in[0];
    const int*   in_lens  = (const int*)d_in[1];
    const int*   out_lens = (const int*)d_in[2];

    zlog_kernel<<<dim3((TQQ + 7) / 8, BB), 256>>>(attn, in_lens, out_lens);
    dp_kernel<<<BB, 128>>>(attn, in_lens, out_lens, (float*)d_out);
}

// round 17
// speedup vs baseline: 1.5835x; 1.2491x over previous
#include <cuda_runtime.h>
#include <cstdint>

#define BB   32
#define TQQ  2000
#define TKK  512
#define EXNEG (-2000000)
#define PBLANK 0.36787944117144233f   /* e^-1 */
#define L2E 1.4426950408889634f
#define FULLW 0xffffffffu
#define RSTR 12                       /* record stride in floats (48B) */

__device__ float    g_loss[BB];
__device__ float    g_logz[BB * TQQ];
__device__ unsigned g_ctr = 0;

__device__ __forceinline__ float ex2f_(float x) {
    float r; asm("ex2.approx.ftz.f32 %0, %1;" : "=f"(r) : "f"(x)); return r;
}

// ---------------------------------------------------------------------------
// Kernel 1: per-row log partition  logZ = log(e^-1 + sum_{j<kl} exp(x)).
// Chunks fully beyond kl are skipped (warp-uniform).
// ---------------------------------------------------------------------------
__global__ __launch_bounds__(256) void zlog_kernel(const float* __restrict__ attn,
                                                   const int* __restrict__ in_lens,
                                                   const int* __restrict__ out_lens) {
    int b    = blockIdx.y;
    int warp = threadIdx.x >> 5;
    int lane = threadIdx.x & 31;
    int t    = blockIdx.x * 8 + warp;
    if (t >= TQQ) return;
    int kl = min(max(in_lens[b], 1), TKK);
    int ql = min(max(out_lens[b], 1), TQQ);
    if (t >= ql) return;

    const float4* row = (const float4*)(attn + ((size_t)b * TQQ + t) * TKK);
    float s = 0.f;
#pragma unroll
    for (int k = 0; k < 4; k++) {
        if (128 * k < kl) {
            float4 v = __ldg(row + lane + 32 * k);
            int j = 4 * (lane + 32 * k);
            float a0 = (j + 0 < kl) ? __expf(v.x) : 0.f;
            float a1 = (j + 1 < kl) ? __expf(v.y) : 0.f;
            float a2 = (j + 2 < kl) ? __expf(v.z) : 0.f;
            float a3 = (j + 3 < kl) ? __expf(v.w) : 0.f;
            s += (a0 + a1) + (a2 + a3);
        }
    }
#pragma unroll
    for (int o = 16; o; o >>= 1) s += __shfl_xor_sync(FULLW, s, o);
    if (lane == 0) g_logz[b * TQQ + t] = __logf(PBLANK + s);
}

// ---------------------------------------------------------------------------
// Kernel 2: CTC forward recursion, 256 threads (2 warps/SMSP), 4 states per
// thread (states 4i..4i+3), 4 steps per exchange/barrier, lazy block
// floating point, EX2 emissions in-loop, 8-row float2 prefetch with pointer
// refill. Halo = 8 states = TWO left-neighbor smem records (12 floats each):
//   q0 = (exo, kk, e_o0_r0, e_o0_r1)   q1 = (4 states)   q2 = (e_o1_r0/1/2, pad)
// Invariant: true_state = c4[j] * 2^(exo - kk).
// ---------------------------------------------------------------------------
__global__ __launch_bounds__(256, 1) void dp_kernel(const float* __restrict__ attn,
                                                    const int* __restrict__ in_lens,
                                                    const int* __restrict__ out_lens,
                                                    float* __restrict__ out) {
    __shared__ float rec[2][258 * RSTR];   // slots 0,1 = constant left pads
    __shared__ float sm_even[513];
    __shared__ float sm_odd[513];
    __shared__ int   sm_ex[513];
    __shared__ float red[256];

    int b    = blockIdx.x;
    int tid  = threadIdx.x;
    int warp = tid >> 5;
    int kl = min(max(in_lens[b], 1), TKK);
    int ql = min(max(out_lens[b], 1), TQQ);

    // thread's two label columns are 2*tid, 2*tid+1 -> one float2 per row
    const float2* eb = (const float2*)(attn + (size_t)b * TQQ * TKK) + tid;

    bool wact = (64 * warp) <= kl;        // warp covers states 128*warp..+127
    float bk0 = (2 * tid     < kl) ? L2E : -1e30f;
    float bk1 = (2 * tid + 1 < kl) ? L2E : -1e30f;

    if (tid < 4) {                        // zero pads, both parities
        float* z = &rec[tid >> 1][(tid & 1) * RSTR];
#pragma unroll
        for (int k = 0; k < RSTR; k++) z[k] = 0.f;
        z[0] = __int_as_float(EXNEG);     // exo
    }

    // ---- row 0 init (B_0 = A_0) ----
    float c4[4];
#pragma unroll
    for (int k = 0; k < 4; k++) c4[k] = 0.f;
    float a1024 = 0.f;
    int   exo   = EXNEG;
    int   kk    = 0;
    if (tid == 0) {
        c4[0] = PBLANK;
        c4[1] = __expf(__ldg(attn + (size_t)b * TQQ * TKK));
        exo = 0;
    }

    // ---- prefetch rows 1..8 (float2 per row) ----
    int qm = ql - 1;
    float2 xs0 = __ldg(eb + (size_t)min(1, qm) * 256);
    float2 xs1 = __ldg(eb + (size_t)min(2, qm) * 256);
    float2 xs2 = __ldg(eb + (size_t)min(3, qm) * 256);
    float2 xs3 = __ldg(eb + (size_t)min(4, qm) * 256);
    float2 xs4 = __ldg(eb + (size_t)min(5, qm) * 256);
    float2 xs5 = __ldg(eb + (size_t)min(6, qm) * 256);
    float2 xs6 = __ldg(eb + (size_t)min(7, qm) * 256);
    float2 xs7 = __ldg(eb + (size_t)min(8, qm) * 256);

    const float2* rp = eb + (size_t)9 * 256;
    int t = 1;

#define EMIT(XC, BK) ex2f_(fmaf((XC), L2E, (BK)))
#define PAIR(DST, SRC, J, EM)                                                  \
    { float se_ = SRC[J] + SRC[J - 1]; DST[J] = se_;                           \
      DST[J + 1] = (SRC[J + 1] + se_) * (EM); }

#define GROUP(S0, S1, S2, S3, REFILL, GUARDED)                                 \
    {                                                                          \
        int p_ = ((t - 1) >> 2) & 1;                                           \
        float e0r0, e0r1, e0r2, e0r3, e1r0, e1r1, e1r2, e1r3;                  \
        if (wact) {                                                            \
            e0r0 = EMIT((S0).x, bk0); e1r0 = EMIT((S0).y, bk1);                \
            e0r1 = EMIT((S1).x, bk0); e1r1 = EMIT((S1).y, bk1);                \
            e0r2 = EMIT((S2).x, bk0); e1r2 = EMIT((S2).y, bk1);                \
            e0r3 = EMIT((S3).x, bk0); e1r3 = EMIT((S3).y, bk1);                \
            if ((REFILL) == 1) {                                               \
                (S0) = __ldg(rp);                                              \
                (S1) = __ldg(rp + 256);                                        \
                (S2) = __ldg(rp + 512);                                        \
                (S3) = __ldg(rp + 768);                                        \
                rp += 1024;                                                    \
            } else if ((REFILL) == 2) {                                        \
                (S0) = __ldg(eb + (size_t)min(t + 8,  qm) * 256);              \
                (S1) = __ldg(eb + (size_t)min(t + 9,  qm) * 256);              \
                (S2) = __ldg(eb + (size_t)min(t + 10, qm) * 256);              \
                (S3) = __ldg(eb + (size_t)min(t + 11, qm) * 256);              \
            }                                                                  \
            float4* wb = (float4*)&rec[p_][(tid + 2) * RSTR];                  \
            wb[0] = make_float4(__int_as_float(exo), __int_as_float(kk),       \
                                e0r0, e0r1);                                   \
            wb[1] = make_float4(c4[0], c4[1], c4[2], c4[3]);                   \
            wb[2] = make_float4(e1r0, e1r1, e1r2, 0.f);                        \
        }                                                                      \
        __syncthreads();                                                       \
        if (wact) {                                                            \
            const float4* r1 = (const float4*)&rec[p_][(tid + 1) * RSTR];      \
            const float4* r2 = (const float4*)&rec[p_][tid * RSTR];            \
            float4 p0 = r1[0], p1 = r1[1], p2 = r1[2];                         \
            float4 u0 = r2[0], u1 = r2[1], u2 = r2[2];                         \
            int e1_ = __float_as_int(p0.x), k1_ = __float_as_int(p0.y);        \
            float L1o0r0 = p0.z, L1o0r1 = p0.w;                                \
            float L1o1r0 = p2.x, L1o1r1 = p2.y, L1o1r2 = p2.z;                 \
            int e2_ = __float_as_int(u0.x), k2_ = __float_as_int(u0.y);        \
            float L2o1r0 = u2.x;                                               \
            int bse = max(exo, max(e1_, e2_));                                 \
            int dO = 127 + (exo - kk)  - bse; if (dO < 0) dO = 0;              \
            int d1 = 127 + (e1_ - k1_) - bse; if (d1 < 0) d1 = 0;              \
            int d2 = 127 + (e2_ - k2_) - bse; if (d2 < 0) d2 = 0;              \
            float sO = __int_as_float(dO << 23);                               \
            float s1 = __int_as_float(d1 << 23);                               \
            float s2 = __int_as_float(d2 << 23);                               \
            float S_[12], T_[12];                                              \
            S_[0] = u1.x * s2; S_[1] = u1.y * s2;                              \
            S_[2] = u1.z * s2; S_[3] = u1.w * s2;                              \
            S_[4] = p1.x * s1; S_[5] = p1.y * s1;                              \
            S_[6] = p1.z * s1; S_[7] = p1.w * s1;                              \
            S_[8]  = c4[0] * sO; S_[9]  = c4[1] * sO;                          \
            S_[10] = c4[2] * sO; S_[11] = c4[3] * sO;                          \
            float n4 = a1024 * sO;                                             \
            if (!(GUARDED) || (t + 0 < ql)) {                                  \
                PAIR(T_, S_, 2, L2o1r0) PAIR(T_, S_, 4, L1o0r0)                \
                PAIR(T_, S_, 6, L1o1r0)                                        \
                PAIR(T_, S_, 8, e0r0) PAIR(T_, S_, 10, e1r0)                   \
                n4 = n4 + S_[11];                                              \
            } else {                                                           \
                _Pragma("unroll")                                              \
                for (int j_ = 2; j_ < 12; j_++) T_[j_] = S_[j_];               \
            }                                                                  \
            if (!(GUARDED) || (t + 1 < ql)) {                                  \
                PAIR(S_, T_, 4, L1o0r1) PAIR(S_, T_, 6, L1o1r1)                \
                PAIR(S_, T_, 8, e0r1) PAIR(S_, T_, 10, e1r1)                   \
                n4 = n4 + T_[11];                                              \
            } else {                                                           \
                _Pragma("unroll")                                              \
                for (int j_ = 4; j_ < 12; j_++) S_[j_] = T_[j_];               \
            }                                                                  \
            if (!(GUARDED) || (t + 2 < ql)) {                                  \
                PAIR(T_, S_, 6, L1o1r2)                                        \
                PAIR(T_, S_, 8, e0r2) PAIR(T_, S_, 10, e1r2)                   \
                n4 = n4 + S_[11];                                              \
            } else {                                                           \
                _Pragma("unroll")                                              \
                for (int j_ = 6; j_ < 12; j_++) T_[j_] = S_[j_];               \
            }                                                                  \
            if (!(GUARDED) || (t + 3 < ql)) {                                  \
                PAIR(S_, T_, 8, e0r3) PAIR(S_, T_, 10, e1r3)                   \
                n4 = n4 + T_[11];                                              \
            } else {                                                           \
                _Pragma("unroll")                                              \
                for (int j_ = 8; j_ < 12; j_++) S_[j_] = T_[j_];               \
            }                                                                  \
            float m_ = fmaxf(fmaxf(S_[8], S_[9]),                              \
                             fmaxf(fmaxf(S_[10], S_[11]), n4));                \
            c4[0] = S_[8];  c4[1] = S_[9];                                     \
            c4[2] = S_[10]; c4[3] = S_[11];                                    \
            a1024 = n4;                                                        \
            kk  = ((__float_as_int(m_) >> 23) & 255) - 127;                    \
            exo = bse + kk;                                                    \
        }                                                                      \
        t += 4;                                                                \
    }

    while (t + 15 < ql) {
        GROUP(xs0, xs1, xs2, xs3, 1, 0)
        GROUP(xs4, xs5, xs6, xs7, 1, 0)
    }
    while (t + 7 < ql) {
        GROUP(xs0, xs1, xs2, xs3, 2, 0)
        GROUP(xs4, xs5, xs6, xs7, 2, 0)
    }
    if (t + 3 < ql) {
        GROUP(xs0, xs1, xs2, xs3, 0, 0)
        if (t < ql) { GROUP(xs4, xs5, xs6, xs7, 0, 1) }
    } else if (t < ql) {
        GROUP(xs0, xs1, xs2, xs3, 0, 1)
    }

    // ---- epilogue: pairs 2*tid, 2*tid+1; true exponent = exo - kk ----
    sm_even[2 * tid]     = c4[0];
    sm_odd [2 * tid]     = c4[1];
    sm_even[2 * tid + 1] = c4[2];
    sm_odd [2 * tid + 1] = c4[3];
    sm_ex  [2 * tid]     = exo - kk;
    sm_ex  [2 * tid + 1] = exo - kk;
    if (tid == 255) { sm_even[512] = a1024; sm_odd[512] = 0.f; sm_ex[512] = exo - kk; }

    float lz = 0.f;
    for (int tt = tid; tt < ql; tt += 256) lz += g_logz[b * TQQ + tt];
    red[tid] = lz;
    __syncthreads();
#pragma unroll
    for (int s = 128; s; s >>= 1) {
        if (tid < s) red[tid] += red[tid + s];
        __syncthreads();
    }

    if (tid == 0) {
        float mE = sm_even[kl];     int eE = sm_ex[kl];       // state 2kl
        float mL = sm_odd[kl - 1];  int eL = sm_ex[kl - 1];   // state 2kl-1
        double ll;
        if (mE == 0.f && mL == 0.f) {
            ll = -1e9;
        } else {
            int eM = max(mE > 0.f ? eE : EXNEG, mL > 0.f ? eL : EXNEG);
            double s2 = 0.0;
            if (mE > 0.f) s2 += (double)mE * exp2((double)(eE - eM));
            if (mL > 0.f) s2 += (double)mL * exp2((double)(eL - eM));
            ll = log(s2) + (double)eM * 0.6931471805599453;
        }
        ll -= (double)red[0];          // - sum_t log Z_t
        ll -= (double)(ql - 1);        // undo B = A * e^t rescale
        g_loss[b] = (float)(-ll / (double)kl);

        __threadfence();
        unsigned prev = atomicAdd(&g_ctr, 1u);
        if (prev == BB - 1) {
            g_ctr = 0;
            __threadfence();
            float s = 0.f;
            for (int bb = 0; bb < BB; bb++) s += g_loss[bb];
            out[0] = s / (float)BB;
        }
    }
}

extern "C" void kernel_launch(void* const* d_in, const int* in_sizes, int n_in,
                              void* d_out, int out_size) {
    const float* attn     = (const float*)d_in[0];
    const int*   in_lens  = (const int*)d_in[1];
    const int*   out_lens = (const int*)d_in[2];

    zlog_kernel<<<dim3((TQQ + 7) / 8, BB), 256>>>(attn, in_lens, out_lens);
    dp_kernel<<<BB, 256>>>(attn, in_lens, out_lens, (float*)d_out);
}